// round 2
// baseline (speedup 1.0000x reference)
#include <cuda_runtime.h>
#include <stdint.h>

#define IN_DIM 128
#define OUT_DIM 64
#define NH 4
#define DH 16
#define N_MAX 100000
#define E_MAX 1600000

// ---------------- device scratch (no allocations allowed) ----------------
__device__ float g_Wt[IN_DIM * OUT_DIM];              // W transposed: [k][o]
__device__ float g_h[(size_t)N_MAX * OUT_DIM];        // projected features
__device__ float g_ssrc[N_MAX * NH];                  // per-node src scores
__device__ float g_sdst[N_MAX * NH];                  // per-node dst scores
__device__ int   g_deg[N_MAX];
__device__ int   g_rowptr[N_MAX + 1];
__device__ int   g_wpos[N_MAX];
__device__ int   g_csr[E_MAX];                        // src per CSR slot
__device__ int   g_partials[128];                     // scan block partials

// ---------------- fast exp on FMA pipe (avoids MUFU bottleneck) ----------
__device__ __forceinline__ float fast_exp(float x) {
    // exp(x) = 2^(x*log2e) = 2^n * 2^u,  u in [-0.5, 0.5]
    float t = x * 1.4426950408889634f;
    float n = rintf(t);
    float u = t - n;
    float p = 1.33335581464e-3f;
    p = fmaf(p, u, 9.61812910763e-3f);
    p = fmaf(p, u, 5.55041086648e-2f);
    p = fmaf(p, u, 2.40226506959e-1f);
    p = fmaf(p, u, 6.93147180560e-1f);
    p = fmaf(p, u, 1.0f);
    int ni = (int)n;
    return __int_as_float(__float_as_int(p) + (ni << 23));
}

// ---------------- K0: transpose W [64][128] -> Wt [128][64] --------------
__global__ void k_transW(const float* __restrict__ W) {
    int idx = blockIdx.x * blockDim.x + threadIdx.x;   // 8192 threads
    if (idx < IN_DIM * OUT_DIM) {
        int k = idx >> 6;        // 0..127
        int o = idx & 63;        // 0..63
        g_Wt[idx] = W[o * IN_DIM + k];
    }
}

// ---------------- K0b: zero degree histogram -----------------------------
__global__ void k_zero_deg(int n) {
    int idx = blockIdx.x * blockDim.x + threadIdx.x;
    if (idx < n) g_deg[idx] = 0;
}

// ---------------- K1: GEMM h = x @ W^T  (fp32, 64x64 tile) ---------------
__global__ __launch_bounds__(256) void k_gemm(const float* __restrict__ x, int n) {
    __shared__ float xs[64][68];   // [m][k-half], pad 4 -> conflict-free reads
    __shared__ float ws[64][64];   // [k-half][o]

    int tx = threadIdx.x & 15;     // col group (4 cols)
    int ty = threadIdx.x >> 4;     // row group (4 rows)
    int m0 = blockIdx.x * 64;

    float acc[4][4];
#pragma unroll
    for (int i = 0; i < 4; i++)
#pragma unroll
        for (int j = 0; j < 4; j++) acc[i][j] = 0.f;

    for (int kk = 0; kk < IN_DIM; kk += 64) {
#pragma unroll
        for (int i = 0; i < 4; i++) {
            int f4 = threadIdx.x + i * 256;     // 0..1023
            int r  = f4 >> 4;                   // 16 float4 per row
            int c  = f4 & 15;
            float4 v = make_float4(0.f, 0.f, 0.f, 0.f);
            if (m0 + r < n)
                v = *(const float4*)&x[(size_t)(m0 + r) * IN_DIM + kk + c * 4];
            *(float4*)&xs[r][c * 4] = v;
        }
#pragma unroll
        for (int i = 0; i < 4; i++) {
            int f4 = threadIdx.x + i * 256;
            int k  = f4 >> 4;
            int c  = f4 & 15;
            *(float4*)&ws[k][c * 4] = *(const float4*)&g_Wt[(kk + k) * OUT_DIM + c * 4];
        }
        __syncthreads();

#pragma unroll 8
        for (int k = 0; k < 64; k++) {
            float4 wv = *(float4*)&ws[k][tx * 4];
            float xv[4];
#pragma unroll
            for (int i = 0; i < 4; i++) xv[i] = xs[ty * 4 + i][k];
#pragma unroll
            for (int i = 0; i < 4; i++) {
                acc[i][0] = fmaf(xv[i], wv.x, acc[i][0]);
                acc[i][1] = fmaf(xv[i], wv.y, acc[i][1]);
                acc[i][2] = fmaf(xv[i], wv.z, acc[i][2]);
                acc[i][3] = fmaf(xv[i], wv.w, acc[i][3]);
            }
        }
        __syncthreads();
    }

#pragma unroll
    for (int i = 0; i < 4; i++) {
        int row = m0 + ty * 4 + i;
        if (row < n) {
            float4 v = make_float4(acc[i][0], acc[i][1], acc[i][2], acc[i][3]);
            *(float4*)&g_h[(size_t)row * OUT_DIM + tx * 4] = v;
        }
    }
}

// ---------------- K2: per-node attention scores (1 thread = 1 node) ------
__global__ void k_scores(const float* __restrict__ a_src,
                         const float* __restrict__ a_dst, int n) {
    int node = blockIdx.x * blockDim.x + threadIdx.x;
    if (node >= n) return;
    const float* hp = &g_h[(size_t)node * OUT_DIM];
#pragma unroll
    for (int hd = 0; hd < NH; hd++) {
        float s1 = 0.f, s2 = 0.f;
#pragma unroll
        for (int j = 0; j < 4; j++) {
            float4 hv = *(const float4*)&hp[hd * DH + j * 4];
            float4 as = *(const float4*)&a_src[hd * DH + j * 4];
            float4 ad = *(const float4*)&a_dst[hd * DH + j * 4];
            s1 = fmaf(hv.x, as.x, fmaf(hv.y, as.y, fmaf(hv.z, as.z, fmaf(hv.w, as.w, s1))));
            s2 = fmaf(hv.x, ad.x, fmaf(hv.y, ad.y, fmaf(hv.z, ad.z, fmaf(hv.w, ad.w, s2))));
        }
        g_ssrc[node * NH + hd] = s1;
        g_sdst[node * NH + hd] = s2;
    }
}

// ---------------- K3: degree histogram -----------------------------------
__global__ void k_hist(const int* __restrict__ dst, int e) {
    int idx = blockIdx.x * blockDim.x + threadIdx.x;
    if (idx < e) atomicAdd(&g_deg[dst[idx]], 1);
}

// ---------------- K4: 3-step exclusive scan of degrees -------------------
__global__ void k_scan_a(int n) {   // grid: ceil(n/1024), block 1024
    __shared__ int warp_sums[32];
    int i = blockIdx.x * 1024 + threadIdx.x;
    int lane = threadIdx.x & 31, wid = threadIdx.x >> 5;
    int v = (i < n) ? g_deg[i] : 0;
    int s = v;
#pragma unroll
    for (int o = 1; o < 32; o <<= 1) {
        int t = __shfl_up_sync(0xFFFFFFFFu, s, o);
        if (lane >= o) s += t;
    }
    if (lane == 31) warp_sums[wid] = s;
    __syncthreads();
    if (wid == 0) {
        int wsv = warp_sums[lane];
#pragma unroll
        for (int o = 1; o < 32; o <<= 1) {
            int t = __shfl_up_sync(0xFFFFFFFFu, wsv, o);
            if (lane >= o) wsv += t;
        }
        warp_sums[lane] = wsv;
    }
    __syncthreads();
    int off = wid ? warp_sums[wid - 1] : 0;
    int incl = s + off;
    if (i < n) g_rowptr[i] = incl - v;               // local exclusive
    if (threadIdx.x == 1023) g_partials[blockIdx.x] = incl;  // block total
}

__global__ void k_scan_b(int nb) {  // 1 block, 128 threads, nb <= 128
    __shared__ int sm[4];
    int t = threadIdx.x;
    int lane = t & 31, wid = t >> 5;
    int v = (t < nb) ? g_partials[t] : 0;
    int s = v;
#pragma unroll
    for (int o = 1; o < 32; o <<= 1) {
        int x = __shfl_up_sync(0xFFFFFFFFu, s, o);
        if (lane >= o) s += x;
    }
    if (lane == 31) sm[wid] = s;
    __syncthreads();
    int off = 0;
    for (int k = 0; k < wid; k++) off += sm[k];
    g_partials[t] = s + off - v;                      // exclusive
}

__global__ void k_scan_c(int n, int e) {
    int i = blockIdx.x * 1024 + threadIdx.x;
    if (i < n) {
        int r = g_rowptr[i] + g_partials[i >> 10];
        g_rowptr[i] = r;
        g_wpos[i]   = r;
    }
    if (i == 0) g_rowptr[n] = e;
}

// ---------------- K5: reorder edges into CSR (store src only) ------------
__global__ void k_reorder(const int* __restrict__ src,
                          const int* __restrict__ dst, int e) {
    int idx = blockIdx.x * blockDim.x + threadIdx.x;
    if (idx < e) {
        int d = dst[idx];
        int p = atomicAdd(&g_wpos[d], 1);
        g_csr[p] = src[idx];
    }
}

// ---------------- K6: fused softmax + weighted aggregation ---------------
// One warp per dst node. 16 lanes per edge (lane q handles cols 4q..4q+3,
// head = q>>2), 2 edges in flight per warp. Prefetches the next CSR index
// to break the csr->h dependent-load chain. Accumulates numerator and
// denominator together, divides once, writes each output exactly once.
__global__ __launch_bounds__(256) void k_agg(float* __restrict__ out, int n) {
    int w = (blockIdx.x * blockDim.x + threadIdx.x) >> 5;
    if (w >= n) return;                  // uniform per warp
    int lane = threadIdx.x & 31;
    int slot = lane >> 4;                // 0 or 1: which edge of the pair
    int q    = lane & 15;                // 0..15 -> float4 index within 64 cols
    int hd   = q >> 2;

    int start = g_rowptr[w];
    int end   = g_rowptr[w + 1];
    float sdst = g_sdst[w * NH + hd];

    float4 acc = make_float4(0.f, 0.f, 0.f, 0.f);
    float ssum = 0.f;

    int j = start + slot;
    int src_cur = (j < end) ? __ldg(&g_csr[j]) : 0;
    for (; j < end; j += 2) {
        int jn = j + 2;
        int src_nxt = (jn < end) ? __ldg(&g_csr[jn]) : 0;   // prefetch
        int src = src_cur;
        float s = __ldg(&g_ssrc[src * NH + hd]) + sdst;
        float ev = (s > 0.f) ? s : 0.2f * s;       // leaky_relu(0.2)
        float p = fast_exp(ev);                    // unshifted exp: max cancels
        float4 hv = *(const float4*)&g_h[(size_t)src * OUT_DIM + q * 4];
        acc.x = fmaf(p, hv.x, acc.x);
        acc.y = fmaf(p, hv.y, acc.y);
        acc.z = fmaf(p, hv.z, acc.z);
        acc.w = fmaf(p, hv.w, acc.w);
        ssum += p;
        src_cur = src_nxt;
    }

    // combine the two edge slots
    acc.x += __shfl_xor_sync(0xFFFFFFFFu, acc.x, 16);
    acc.y += __shfl_xor_sync(0xFFFFFFFFu, acc.y, 16);
    acc.z += __shfl_xor_sync(0xFFFFFFFFu, acc.z, 16);
    acc.w += __shfl_xor_sync(0xFFFFFFFFu, acc.w, 16);
    ssum  += __shfl_xor_sync(0xFFFFFFFFu, ssum, 16);

    if (slot == 0) {
        float inv = 1.f / fmaxf(ssum, 1e-9f);
        float4 o = make_float4(acc.x * inv, acc.y * inv, acc.z * inv, acc.w * inv);
        *(float4*)&out[(size_t)w * OUT_DIM + q * 4] = o;
    }
}

// ---------------- launch ---------------------------------------------------
extern "C" void kernel_launch(void* const* d_in, const int* in_sizes, int n_in,
                              void* d_out, int out_size) {
    const float* x     = (const float*)d_in[0];
    const float* W     = (const float*)d_in[1];
    const float* a_src = (const float*)d_in[2];
    const float* a_dst = (const float*)d_in[3];
    const int*   ei    = (const int*)d_in[4];

    int n = in_sizes[0] / IN_DIM;
    int e = in_sizes[4] / 2;
    const int* srcp = ei;
    const int* dstp = ei + e;
    float* out = (float*)d_out;

    k_transW  <<<(IN_DIM * OUT_DIM + 255) / 256, 256>>>(W);
    k_zero_deg<<<(n + 255) / 256, 256>>>(n);
    k_gemm    <<<(n + 63) / 64, 256>>>(x, n);
    k_scores  <<<(n + 255) / 256, 256>>>(a_src, a_dst, n);
    k_hist    <<<(e + 255) / 256, 256>>>(dstp, e);
    int nb = (n + 1023) / 1024;
    k_scan_a  <<<nb, 1024>>>(n);
    k_scan_b  <<<1, 128>>>(nb);
    k_scan_c  <<<nb, 1024>>>(n, e);
    k_reorder <<<(e + 255) / 256, 256>>>(srcp, dstp, e);
    k_agg     <<<(n + 7) / 8, 256>>>(out, n);
}